// round 2
// baseline (speedup 1.0000x reference)
#include <cuda_runtime.h>

#define CI 512
#define CO 256
#define HH 28
#define WW 28
#define OH 56
#define OW 56
#define NBATCH 16

#define BM 64
#define BN 64
#define BK 16

// Scratch (allocation-free rule: __device__ globals)
__device__ float g_t1[NBATCH * CO * OH * OW];        // relu(bn1(conv1(up)))
__device__ float g_sc[NBATCH * CO * OH * OW];        // bns(convsc(up))
__device__ float g_wA[25 * CI * (2 * CO)];           // [kh*5+kw][ci][oc]  oc<256: w1, else wsc
__device__ float g_wB[9 * CO * CO];                  // [kh*3+kw][ci][oc]

// ---------------------------------------------------------------------------
// Weight re-layout: [oc][ci][kh][kw] -> [tap][ci][oc] (coalesced GEMM B-tiles)
// ---------------------------------------------------------------------------
__global__ void prep_weights(const float* __restrict__ w1,
                             const float* __restrict__ wsc,
                             const float* __restrict__ w2)
{
    int idx = blockIdx.x * blockDim.x + threadIdx.x;
    const int nA = 25 * CI * (2 * CO);
    const int nB = 9 * CO * CO;
    if (idx < nA) {
        int tap = idx / (CI * 2 * CO);
        int r   = idx % (CI * 2 * CO);
        int ci  = r / (2 * CO);
        int oc  = r % (2 * CO);
        float v = (oc < CO) ? w1[(oc * CI + ci) * 25 + tap]
                            : wsc[((oc - CO) * CI + ci) * 25 + tap];
        g_wA[idx] = v;
    }
    if (idx < nB) {
        int tap = idx / (CO * CO);
        int r   = idx % (CO * CO);
        int ci  = r / CO;
        int oc  = r % CO;
        g_wB[idx] = w2[(oc * CO + ci) * 9 + tap];
    }
}

// ---------------------------------------------------------------------------
// Kernel A: parity-decomposed 5x5 conv on zero-inserted input.
// Per (batch, parity): GEMM  M=784 (28x28), N=512 (t1 || sc), K=512*ntaps.
// ---------------------------------------------------------------------------
__global__ __launch_bounds__(128)
void convA(const float* __restrict__ x,
           const float* __restrict__ g1, const float* __restrict__ b1,
           const float* __restrict__ m1, const float* __restrict__ v1,
           const float* __restrict__ gs, const float* __restrict__ bs,
           const float* __restrict__ ms, const float* __restrict__ vs)
{
    __shared__ float As[BK][BM];
    __shared__ float Bs[BK][BN];

    const int bz    = blockIdx.z;
    const int batch = bz >> 2;
    const int par   = bz & 3;
    const int ph    = par >> 1, pw = par & 1;
    const int nTa   = ph ? 2 : 3;
    const int nTb   = pw ? 2 : 3;
    const int ntaps = nTa * nTb;

    const int m0 = blockIdx.x * BM;   // spatial base in [0, 784)
    const int n0 = blockIdx.y * BN;   // combined-oc base in [0, 512)

    const int tid = threadIdx.x;      // 128 threads
    const int sx  = tid & 15;         // spatial sub-tile (4 positions)
    const int oy  = tid >> 4;         // oc sub-tile (8 channels)
    const int lci = tid >> 3;         // loader: ci row 0..15
    const int lm0 = (tid & 7) * 8;    // loader: column base

    int  mi[8], mj[8];
    bool mvld[8];
#pragma unroll
    for (int u = 0; u < 8; ++u) {
        int mg  = m0 + lm0 + u;
        mvld[u] = (mg < 784);
        int mm  = mvld[u] ? mg : 0;
        mi[u]   = mm / 28;
        mj[u]   = mm % 28;
    }

    const float* xb = x + batch * (CI * HH * WW);

    float acc[4][8];
#pragma unroll
    for (int i = 0; i < 4; ++i)
#pragma unroll
        for (int j = 0; j < 8; ++j) acc[i][j] = 0.f;

    for (int t = 0; t < ntaps; ++t) {
        const int ta = t / nTb;
        const int tb = t - ta * nTb;
        const int da = ph ? ta : ta - 1;       // input row offset
        const int db = pw ? tb : tb - 1;       // input col offset
        const int kh = ph ? 2 * ta + 1 : 2 * ta;
        const int kw = pw ? 2 * tb + 1 : 2 * tb;
        const float* wp = g_wA + (kh * 5 + kw) * (CI * 2 * CO);

        for (int ci0 = 0; ci0 < CI; ci0 += BK) {
            // ---- load A tile (gathered, zero-padded) ----
            const float* xc = xb + (ci0 + lci) * (HH * WW);
#pragma unroll
            for (int u = 0; u < 8; ++u) {
                int ii = mi[u] + da;
                int jj = mj[u] + db;
                float v = 0.f;
                if (mvld[u] && (unsigned)ii < 28u && (unsigned)jj < 28u)
                    v = __ldg(xc + ii * WW + jj);
                As[lci][lm0 + u] = v;
            }
            // ---- load B tile (coalesced float4) ----
            const float* wq = wp + (ci0 + lci) * (2 * CO) + n0 + lm0;
            *(float4*)&Bs[lci][lm0]     = *(const float4*)(wq);
            *(float4*)&Bs[lci][lm0 + 4] = *(const float4*)(wq + 4);
            __syncthreads();

#pragma unroll
            for (int kk = 0; kk < BK; ++kk) {
                float4 a  = *(const float4*)&As[kk][sx * 4];
                float4 b0 = *(const float4*)&Bs[kk][oy * 8];
                float4 b1 = *(const float4*)&Bs[kk][oy * 8 + 4];
                float av[4] = {a.x, a.y, a.z, a.w};
                float bv[8] = {b0.x, b0.y, b0.z, b0.w, b1.x, b1.y, b1.z, b1.w};
#pragma unroll
                for (int i = 0; i < 4; ++i)
#pragma unroll
                    for (int j = 0; j < 8; ++j)
                        acc[i][j] += av[i] * bv[j];
            }
            __syncthreads();
        }
    }

    // ---- epilogue: folded BN (+ReLU for t1 branch), scatter to 56x56 ----
    const bool isT1 = (n0 < CO);   // BN=64 divides CO=256, so a block is single-branch
    float es[8], eb[8];
#pragma unroll
    for (int j = 0; j < 8; ++j) {
        int oc = n0 + oy * 8 + j;
        int c  = isT1 ? oc : oc - CO;
        float sg = isT1 ? g1[c] : gs[c];
        float sb = isT1 ? b1[c] : bs[c];
        float sm = isT1 ? m1[c] : ms[c];
        float sv = isT1 ? v1[c] : vs[c];
        float s  = sg * rsqrtf(sv + 1e-5f);
        es[j] = s;
        eb[j] = sb - sm * s;
    }
    float* outp = isT1 ? g_t1 : g_sc;
#pragma unroll
    for (int i = 0; i < 4; ++i) {
        int mg = m0 + sx * 4 + i;
        if (mg >= 784) continue;
        int oh = 2 * (mg / 28) + ph;
        int ow = 2 * (mg % 28) + pw;
#pragma unroll
        for (int j = 0; j < 8; ++j) {
            int oc = n0 + oy * 8 + j;
            int c  = isT1 ? oc : oc - CO;
            float v = acc[i][j] * es[j] + eb[j];
            if (isT1) v = fmaxf(v, 0.f);
            outp[((batch * CO + c) * OH + oh) * OW + ow] = v;
        }
    }
}

// ---------------------------------------------------------------------------
// Kernel B: 3x3 conv over t1 + BN2 + shortcut add + ReLU -> d_out.
// Per batch: GEMM  M=3136, N=256, K=256*9.
// ---------------------------------------------------------------------------
__global__ __launch_bounds__(128)
void convB(const float* __restrict__ g2, const float* __restrict__ b2,
           const float* __restrict__ m2, const float* __restrict__ v2,
           float* __restrict__ out)
{
    __shared__ float As[BK][BM];
    __shared__ float Bs[BK][BN];

    const int batch = blockIdx.z;
    const int m0 = blockIdx.x * BM;   // 49 tiles, exact
    const int n0 = blockIdx.y * BN;   // 4 tiles

    const int tid = threadIdx.x;
    const int sx  = tid & 15;
    const int oy  = tid >> 4;
    const int lci = tid >> 3;
    const int lm0 = (tid & 7) * 8;

    int mi[8], mj[8];
#pragma unroll
    for (int u = 0; u < 8; ++u) {
        int mg = m0 + lm0 + u;        // always < 3136
        mi[u] = mg / 56;
        mj[u] = mg % 56;
    }

    const float* xb = g_t1 + batch * (CO * OH * OW);

    float acc[4][8];
#pragma unroll
    for (int i = 0; i < 4; ++i)
#pragma unroll
        for (int j = 0; j < 8; ++j) acc[i][j] = 0.f;

    for (int t = 0; t < 9; ++t) {
        const int da = t / 3 - 1;
        const int db = t % 3 - 1;
        const float* wp = g_wB + t * (CO * CO);

        for (int ci0 = 0; ci0 < CO; ci0 += BK) {
            const float* xc = xb + (ci0 + lci) * (OH * OW);
#pragma unroll
            for (int u = 0; u < 8; ++u) {
                int ii = mi[u] + da;
                int jj = mj[u] + db;
                float v = 0.f;
                if ((unsigned)ii < 56u && (unsigned)jj < 56u)
                    v = __ldg(xc + ii * OW + jj);
                As[lci][lm0 + u] = v;
            }
            const float* wq = wp + (ci0 + lci) * CO + n0 + lm0;
            *(float4*)&Bs[lci][lm0]     = *(const float4*)(wq);
            *(float4*)&Bs[lci][lm0 + 4] = *(const float4*)(wq + 4);
            __syncthreads();

#pragma unroll
            for (int kk = 0; kk < BK; ++kk) {
                float4 a  = *(const float4*)&As[kk][sx * 4];
                float4 b0 = *(const float4*)&Bs[kk][oy * 8];
                float4 b1 = *(const float4*)&Bs[kk][oy * 8 + 4];
                float av[4] = {a.x, a.y, a.z, a.w};
                float bv[8] = {b0.x, b0.y, b0.z, b0.w, b1.x, b1.y, b1.z, b1.w};
#pragma unroll
                for (int i = 0; i < 4; ++i)
#pragma unroll
                    for (int j = 0; j < 8; ++j)
                        acc[i][j] += av[i] * bv[j];
            }
            __syncthreads();
        }
    }

    float es[8], eb[8];
#pragma unroll
    for (int j = 0; j < 8; ++j) {
        int oc = n0 + oy * 8 + j;
        float s = g2[oc] * rsqrtf(v2[oc] + 1e-5f);
        es[j] = s;
        eb[j] = b2[oc] - m2[oc] * s;
    }
#pragma unroll
    for (int i = 0; i < 4; ++i) {
        int mg = m0 + sx * 4 + i;
        int oh = mg / 56;
        int ow = mg % 56;
#pragma unroll
        for (int j = 0; j < 8; ++j) {
            int oc  = n0 + oy * 8 + j;
            int idx = ((batch * CO + oc) * OH + oh) * OW + ow;
            float v = acc[i][j] * es[j] + eb[j] + g_sc[idx];
            out[idx] = fmaxf(v, 0.f);
        }
    }
}

// ---------------------------------------------------------------------------
extern "C" void kernel_launch(void* const* d_in, const int* in_sizes, int n_in,
                              void* d_out, int out_size)
{
    const float* x   = (const float*)d_in[0];
    const float* w1  = (const float*)d_in[1];
    const float* g1  = (const float*)d_in[2];
    const float* b1  = (const float*)d_in[3];
    const float* m1  = (const float*)d_in[4];
    const float* v1  = (const float*)d_in[5];
    const float* w2  = (const float*)d_in[6];
    const float* g2  = (const float*)d_in[7];
    const float* b2  = (const float*)d_in[8];
    const float* m2  = (const float*)d_in[9];
    const float* v2  = (const float*)d_in[10];
    const float* wsc = (const float*)d_in[11];
    const float* gs  = (const float*)d_in[12];
    const float* bs  = (const float*)d_in[13];
    const float* ms  = (const float*)d_in[14];
    const float* vs  = (const float*)d_in[15];
    float* out = (float*)d_out;

    const int nprep = 25 * CI * (2 * CO);
    prep_weights<<<(nprep + 255) / 256, 256>>>(w1, wsc, w2);

    dim3 gA(13, 8, NBATCH * 4);            // 784 -> 13 M-tiles (guarded), 512 oc
    convA<<<gA, 128>>>(x, g1, b1, m1, v1, gs, bs, ms, vs);

    dim3 gB(49, 4, NBATCH);                // 3136 = 49*64 exact, 256 oc
    convB<<<gB, 128>>>(g2, b2, m2, v2, out);
}

// round 3
// speedup vs baseline: 1.0430x; 1.0430x over previous
#include <cuda_runtime.h>

#define CI 512
#define CO 256
#define HH 28
#define WW 28
#define OH 56
#define OW 56
#define NBATCH 16

#define BM 64
#define BN 64
#define BK 16

// Packed fp32x2 helpers (Blackwell FFMA2 — only reachable via PTX)
#define PACK2(d, x) asm("mov.b64 %0, {%1, %1};" : "=l"(d) : "r"(__float_as_uint(x)))
#define FMA2(d, a, b) asm("fma.rn.f32x2 %0, %1, %2, %0;" : "+l"(d) : "l"(a), "l"(b))
#define UNPACK2(lo, hi, v) asm("mov.b64 {%0, %1}, %2;" : "=r"(lo), "=r"(hi) : "l"(v))

// Scratch (allocation-free rule: __device__ globals)
__device__ float g_t1[NBATCH * CO * OH * OW];        // relu(bn1(conv1(up)))
__device__ float g_sc[NBATCH * CO * OH * OW];        // bns(convsc(up))
__device__ float g_wA[25 * CI * (2 * CO)];           // [kh*5+kw][ci][oc]  oc<256: w1, else wsc
__device__ float g_wB[9 * CO * CO];                  // [kh*3+kw][ci][oc]

// ---------------------------------------------------------------------------
// Weight re-layout: [oc][ci][kh][kw] -> [tap][ci][oc] (coalesced GEMM B-tiles)
// ---------------------------------------------------------------------------
__global__ void prep_weights(const float* __restrict__ w1,
                             const float* __restrict__ wsc,
                             const float* __restrict__ w2)
{
    int idx = blockIdx.x * blockDim.x + threadIdx.x;
    const int nA = 25 * CI * (2 * CO);
    const int nB = 9 * CO * CO;
    if (idx < nA) {
        int tap = idx / (CI * 2 * CO);
        int r   = idx % (CI * 2 * CO);
        int ci  = r / (2 * CO);
        int oc  = r % (2 * CO);
        float v = (oc < CO) ? w1[(oc * CI + ci) * 25 + tap]
                            : wsc[((oc - CO) * CI + ci) * 25 + tap];
        g_wA[idx] = v;
    }
    if (idx < nB) {
        int tap = idx / (CO * CO);
        int r   = idx % (CO * CO);
        int ci  = r / CO;
        int oc  = r % CO;
        g_wB[idx] = w2[(oc * CO + ci) * 9 + tap];
    }
}

// ---------------------------------------------------------------------------
// Kernel A: parity-decomposed 5x5 conv on zero-inserted input.
// Per (batch, parity): GEMM  M=784 (28x28), N=512 (t1 || sc), K=512*ntaps.
// ---------------------------------------------------------------------------
__global__ __launch_bounds__(128)
void convA(const float* __restrict__ x,
           const float* __restrict__ g1, const float* __restrict__ b1,
           const float* __restrict__ m1, const float* __restrict__ v1,
           const float* __restrict__ gs, const float* __restrict__ bs,
           const float* __restrict__ ms, const float* __restrict__ vs)
{
    __shared__ float As[BK][BM];
    __shared__ float Bs[BK][BN];

    const int bz    = blockIdx.z;
    const int batch = bz >> 2;
    const int par   = bz & 3;
    const int ph    = par >> 1, pw = par & 1;
    const int nTa   = ph ? 2 : 3;
    const int nTb   = pw ? 2 : 3;
    const int ntaps = nTa * nTb;

    const int m0 = blockIdx.x * BM;   // spatial base in [0, 784)
    const int n0 = blockIdx.y * BN;   // combined-oc base in [0, 512)

    const int tid = threadIdx.x;      // 128 threads
    const int sx  = tid & 15;         // spatial sub-tile (4 positions)
    const int oy  = tid >> 4;         // oc sub-tile (8 channels = 4 f32x2 pairs)
    const int lci = tid >> 3;         // loader: ci row 0..15
    const int lm0 = (tid & 7) * 8;    // loader: column base

    int  mi[8], mj[8];
    bool mvld[8];
#pragma unroll
    for (int u = 0; u < 8; ++u) {
        int mg  = m0 + lm0 + u;
        mvld[u] = (mg < 784);
        int mm  = mvld[u] ? mg : 0;
        mi[u]   = mm / 28;
        mj[u]   = mm % 28;
    }

    const float* xb = x + batch * (CI * HH * WW);

    unsigned long long acc2[4][4];
#pragma unroll
    for (int i = 0; i < 4; ++i)
#pragma unroll
        for (int j = 0; j < 4; ++j) acc2[i][j] = 0ull;

    for (int t = 0; t < ntaps; ++t) {
        const int ta = t / nTb;
        const int tb = t - ta * nTb;
        const int da = ph ? ta : ta - 1;       // input row offset
        const int db = pw ? tb : tb - 1;       // input col offset
        const int kh = ph ? 2 * ta + 1 : 2 * ta;
        const int kw = pw ? 2 * tb + 1 : 2 * tb;
        const float* wp = g_wA + (kh * 5 + kw) * (CI * 2 * CO);

        for (int ci0 = 0; ci0 < CI; ci0 += BK) {
            // ---- load A tile (gathered, zero-padded) ----
            const float* xc = xb + (ci0 + lci) * (HH * WW);
#pragma unroll
            for (int u = 0; u < 8; ++u) {
                int ii = mi[u] + da;
                int jj = mj[u] + db;
                float v = 0.f;
                if (mvld[u] && (unsigned)ii < 28u && (unsigned)jj < 28u)
                    v = __ldg(xc + ii * WW + jj);
                As[lci][lm0 + u] = v;
            }
            // ---- load B tile (coalesced float4) ----
            const float* wq = wp + (ci0 + lci) * (2 * CO) + n0 + lm0;
            *(float4*)&Bs[lci][lm0]     = *(const float4*)(wq);
            *(float4*)&Bs[lci][lm0 + 4] = *(const float4*)(wq + 4);
            __syncthreads();

#pragma unroll
            for (int kk = 0; kk < BK; ++kk) {
                float4 a = *(const float4*)&As[kk][sx * 4];
                unsigned long long av2[4];
                PACK2(av2[0], a.x); PACK2(av2[1], a.y);
                PACK2(av2[2], a.z); PACK2(av2[3], a.w);
                const unsigned long long* bp =
                    (const unsigned long long*)&Bs[kk][oy * 8];
                unsigned long long bv2[4] = {bp[0], bp[1], bp[2], bp[3]};
#pragma unroll
                for (int i = 0; i < 4; ++i)
#pragma unroll
                    for (int j = 0; j < 4; ++j)
                        FMA2(acc2[i][j], av2[i], bv2[j]);
            }
            __syncthreads();
        }
    }

    // ---- epilogue: folded BN (+ReLU for t1 branch), scatter to 56x56 ----
    const bool isT1 = (n0 < CO);   // BN=64 divides CO=256, so a block is single-branch
    float es[8], eb[8];
#pragma unroll
    for (int j = 0; j < 8; ++j) {
        int oc = n0 + oy * 8 + j;
        int c  = isT1 ? oc : oc - CO;
        float sg = isT1 ? g1[c] : gs[c];
        float sb = isT1 ? b1[c] : bs[c];
        float sm = isT1 ? m1[c] : ms[c];
        float sv = isT1 ? v1[c] : vs[c];
        float s  = sg * rsqrtf(sv + 1e-5f);
        es[j] = s;
        eb[j] = sb - sm * s;
    }
    float* outp = isT1 ? g_t1 : g_sc;
#pragma unroll
    for (int i = 0; i < 4; ++i) {
        int mg = m0 + sx * 4 + i;
        if (mg >= 784) continue;
        int oh = 2 * (mg / 28) + ph;
        int ow = 2 * (mg % 28) + pw;
#pragma unroll
        for (int j = 0; j < 4; ++j) {
            unsigned int ulo, uhi;
            UNPACK2(ulo, uhi, acc2[i][j]);
            float f0 = __uint_as_float(ulo);
            float f1 = __uint_as_float(uhi);
            int oc0 = n0 + oy * 8 + 2 * j;
            int c0  = isT1 ? oc0 : oc0 - CO;
            float v0 = f0 * es[2 * j] + eb[2 * j];
            float v1o = f1 * es[2 * j + 1] + eb[2 * j + 1];
            if (isT1) { v0 = fmaxf(v0, 0.f); v1o = fmaxf(v1o, 0.f); }
            outp[((batch * CO + c0) * OH + oh) * OW + ow] = v0;
            outp[((batch * CO + c0 + 1) * OH + oh) * OW + ow] = v1o;
        }
    }
}

// ---------------------------------------------------------------------------
// Kernel B: 3x3 conv over t1 + BN2 + shortcut add + ReLU -> d_out.
// Per batch: GEMM  M=3136, N=256, K=256*9.
// ---------------------------------------------------------------------------
__global__ __launch_bounds__(128)
void convB(const float* __restrict__ g2, const float* __restrict__ b2,
           const float* __restrict__ m2, const float* __restrict__ v2,
           float* __restrict__ out)
{
    __shared__ float As[BK][BM];
    __shared__ float Bs[BK][BN];

    const int batch = blockIdx.z;
    const int m0 = blockIdx.x * BM;   // 49 tiles, exact
    const int n0 = blockIdx.y * BN;   // 4 tiles

    const int tid = threadIdx.x;
    const int sx  = tid & 15;
    const int oy  = tid >> 4;
    const int lci = tid >> 3;
    const int lm0 = (tid & 7) * 8;

    int mi[8], mj[8];
#pragma unroll
    for (int u = 0; u < 8; ++u) {
        int mg = m0 + lm0 + u;        // always < 3136
        mi[u] = mg / 56;
        mj[u] = mg % 56;
    }

    const float* xb = g_t1 + batch * (CO * OH * OW);

    unsigned long long acc2[4][4];
#pragma unroll
    for (int i = 0; i < 4; ++i)
#pragma unroll
        for (int j = 0; j < 4; ++j) acc2[i][j] = 0ull;

    for (int t = 0; t < 9; ++t) {
        const int da = t / 3 - 1;
        const int db = t % 3 - 1;
        const float* wp = g_wB + t * (CO * CO);

        for (int ci0 = 0; ci0 < CO; ci0 += BK) {
            const float* xc = xb + (ci0 + lci) * (OH * OW);
#pragma unroll
            for (int u = 0; u < 8; ++u) {
                int ii = mi[u] + da;
                int jj = mj[u] + db;
                float v = 0.f;
                if ((unsigned)ii < 56u && (unsigned)jj < 56u)
                    v = __ldg(xc + ii * OW + jj);
                As[lci][lm0 + u] = v;
            }
            const float* wq = wp + (ci0 + lci) * CO + n0 + lm0;
            *(float4*)&Bs[lci][lm0]     = *(const float4*)(wq);
            *(float4*)&Bs[lci][lm0 + 4] = *(const float4*)(wq + 4);
            __syncthreads();

#pragma unroll
            for (int kk = 0; kk < BK; ++kk) {
                float4 a = *(const float4*)&As[kk][sx * 4];
                unsigned long long av2[4];
                PACK2(av2[0], a.x); PACK2(av2[1], a.y);
                PACK2(av2[2], a.z); PACK2(av2[3], a.w);
                const unsigned long long* bp =
                    (const unsigned long long*)&Bs[kk][oy * 8];
                unsigned long long bv2[4] = {bp[0], bp[1], bp[2], bp[3]};
#pragma unroll
                for (int i = 0; i < 4; ++i)
#pragma unroll
                    for (int j = 0; j < 4; ++j)
                        FMA2(acc2[i][j], av2[i], bv2[j]);
            }
            __syncthreads();
        }
    }

    float es[8], eb[8];
#pragma unroll
    for (int j = 0; j < 8; ++j) {
        int oc = n0 + oy * 8 + j;
        float s = g2[oc] * rsqrtf(v2[oc] + 1e-5f);
        es[j] = s;
        eb[j] = b2[oc] - m2[oc] * s;
    }
#pragma unroll
    for (int i = 0; i < 4; ++i) {
        int mg = m0 + sx * 4 + i;
        int oh = mg / 56;
        int ow = mg % 56;
#pragma unroll
        for (int j = 0; j < 4; ++j) {
            unsigned int ulo, uhi;
            UNPACK2(ulo, uhi, acc2[i][j]);
            float f0 = __uint_as_float(ulo);
            float f1 = __uint_as_float(uhi);
            int oc0  = n0 + oy * 8 + 2 * j;
            int idx0 = ((batch * CO + oc0) * OH + oh) * OW + ow;
            int idx1 = idx0 + OH * OW;
            float v0 = f0 * es[2 * j] + eb[2 * j] + g_sc[idx0];
            float v1o = f1 * es[2 * j + 1] + eb[2 * j + 1] + g_sc[idx1];
            out[idx0] = fmaxf(v0, 0.f);
            out[idx1] = fmaxf(v1o, 0.f);
        }
    }
}

// ---------------------------------------------------------------------------
extern "C" void kernel_launch(void* const* d_in, const int* in_sizes, int n_in,
                              void* d_out, int out_size)
{
    const float* x   = (const float*)d_in[0];
    const float* w1  = (const float*)d_in[1];
    const float* g1  = (const float*)d_in[2];
    const float* b1  = (const float*)d_in[3];
    const float* m1  = (const float*)d_in[4];
    const float* v1  = (const float*)d_in[5];
    const float* w2  = (const float*)d_in[6];
    const float* g2  = (const float*)d_in[7];
    const float* b2  = (const float*)d_in[8];
    const float* m2  = (const float*)d_in[9];
    const float* v2  = (const float*)d_in[10];
    const float* wsc = (const float*)d_in[11];
    const float* gs  = (const float*)d_in[12];
    const float* bs  = (const float*)d_in[13];
    const float* ms  = (const float*)d_in[14];
    const float* vs  = (const float*)d_in[15];
    float* out = (float*)d_out;

    const int nprep = 25 * CI * (2 * CO);
    prep_weights<<<(nprep + 255) / 256, 256>>>(w1, wsc, w2);

    dim3 gA(13, 8, NBATCH * 4);            // 784 -> 13 M-tiles (guarded), 512 oc
    convA<<<gA, 128>>>(x, g1, b1, m1, v1, gs, bs, ms, vs);

    dim3 gB(49, 4, NBATCH);                // 3136 = 49*64 exact, 256 oc
    convB<<<gB, 128>>>(g2, b2, m2, v2, out);
}

// round 5
// speedup vs baseline: 3.7478x; 3.5933x over previous
#include <cuda_runtime.h>
#include <cuda_bf16.h>
#include <stdint.h>

#define CIn 512
#define COc 256
#define NB  16

// ---------------- device scratch (allocation-free) --------------------------
__device__ uint32_t g_x2 [NB * CIn * 28 * 28];       // packed bf16 hi|lo<<16 of x
__device__ uint32_t g_t1x2[NB * COc * 56 * 56];      // packed split of t1
__device__ float    g_scf [NB * COc * 56 * 56];      // shortcut (fp32)
__device__ __nv_bfloat16 g_wAh[25 * 32 * 4 * 2048];  // frag-order weight images (hi)
__device__ __nv_bfloat16 g_wAl[25 * 32 * 4 * 2048];  // (lo)
__device__ __nv_bfloat16 g_wBh[9 * 16 * 2 * 2048];
__device__ __nv_bfloat16 g_wBl[9 * 16 * 2 * 2048];

// ---------------- helpers ---------------------------------------------------
__device__ __forceinline__ uint32_t pack_split(float v) {
    __nv_bfloat16 h = __float2bfloat16(v);
    float r = v - __bfloat162float(h);
    __nv_bfloat16 l = __float2bfloat16(r);
    return (uint32_t)__bfloat16_as_ushort(h) | ((uint32_t)__bfloat16_as_ushort(l) << 16);
}
__device__ __forceinline__ void mma16816(float* c, const uint32_t* a, const uint32_t* b) {
    asm volatile(
        "mma.sync.aligned.m16n8k16.row.col.f32.bf16.bf16.f32 "
        "{%0,%1,%2,%3},{%4,%5,%6,%7},{%8,%9},{%0,%1,%2,%3};"
        : "+f"(c[0]), "+f"(c[1]), "+f"(c[2]), "+f"(c[3])
        : "r"(a[0]), "r"(a[1]), "r"(a[2]), "r"(a[3]), "r"(b[0]), "r"(b[1]));
}

// Fragment-order index for a weight element (k within k16, n within n8-group).
// b0 = B[2(l&3)+h][l>>2], b1 = k+8.  elem index (bf16) inside 2048-elt image:
__device__ __forceinline__ int bfrag_idx(int nf, int n, int kk) {
    int lane = n * 4 + ((kk & 7) >> 1);
    return nf * 128 + lane * 4 + (kk >> 3) * 2 + (kk & 1);
}

// ---------------- prep: pack x, build frag-order weight images --------------
__global__ void prep(const float* __restrict__ x,  const float* __restrict__ w1,
                     const float* __restrict__ wsc, const float* __restrict__ w2)
{
    int idx = blockIdx.x * blockDim.x + threadIdx.x;
    const int nX  = NB * CIn * 28 * 28;     // 6,422,528
    const int nA  = 25 * CIn * 512;         // 6,553,600
    const int nBw = 9 * COc * COc;          // 589,824
    if (idx < nX) g_x2[idx] = pack_split(x[idx]);
    if (idx < nA) {
        int tap = idx / (CIn * 512);
        int rr  = idx % (CIn * 512);
        int ci  = rr / 512;
        int oc  = rr % 512;
        float v = (oc < COc) ? w1[(oc * CIn + ci) * 25 + tap]
                             : wsc[((oc - COc) * CIn + ci) * 25 + tap];
        __nv_bfloat16 h = __float2bfloat16(v);
        __nv_bfloat16 l = __float2bfloat16(v - __bfloat162float(h));
        int ntile = oc >> 7, nl = oc & 127, nf = nl >> 3, n = nl & 7;
        int kc16 = ci >> 4, kk = ci & 15;
        int e = ((tap * 32 + kc16) * 4 + ntile) * 2048 + bfrag_idx(nf, n, kk);
        g_wAh[e] = h; g_wAl[e] = l;
    }
    if (idx < nBw) {
        int tap = idx / (COc * COc);
        int rr  = idx % (COc * COc);
        int ci  = rr / COc;
        int oc  = rr % COc;
        float v = w2[(oc * COc + ci) * 9 + tap];
        __nv_bfloat16 h = __float2bfloat16(v);
        __nv_bfloat16 l = __float2bfloat16(v - __bfloat162float(h));
        int ntile = oc >> 7, nl = oc & 127, nf = nl >> 3, n = nl & 7;
        int kc16 = ci >> 4, kk = ci & 15;
        int e = ((tap * 16 + kc16) * 2 + ntile) * 2048 + bfrag_idx(nf, n, kk);
        g_wBh[e] = h; g_wBl[e] = l;
    }
}

// ---------------- smem layout (shared by both GEMM kernels) -----------------
// GEMM phase: AH[2][4096] AL[2][4096] BH[2][4096] BL[2][4096]  (32 KB)
// Epilogue:   float stage[64*132] (33792 B) overlaps everything.
#define SM_BYTES 33792

// Common macro body for the MMA mainloop chunk compute.
#define MMA_CHUNK(AH, AL, BH, BL)                                              \
    _Pragma("unroll")                                                          \
    for (int s = 0; s < 2; ++s) {                                              \
        uint32_t bh[4][2], bl[4][2];                                           \
        _Pragma("unroll")                                                      \
        for (int nfl = 0; nfl < 4; ++nfl) {                                    \
            const uint32_t* pb =                                               \
                (const uint32_t*)(BH + s * 4096 + (wn * 4 + nfl) * 256 + lane * 8); \
            bh[nfl][0] = pb[0]; bh[nfl][1] = pb[1];                            \
            const uint32_t* pl =                                               \
                (const uint32_t*)(BL + s * 4096 + (wn * 4 + nfl) * 256 + lane * 8); \
            bl[nfl][0] = pl[0]; bl[nfl][1] = pl[1];                            \
        }                                                                      \
        _Pragma("unroll")                                                      \
        for (int mfl = 0; mfl < 4; ++mfl) {                                    \
            uint4 ahv = *(const uint4*)(AH + s * 4096 + (wm * 4 + mfl) * 512 + lane * 16); \
            uint4 alv = *(const uint4*)(AL + s * 4096 + (wm * 4 + mfl) * 512 + lane * 16); \
            uint32_t ah[4] = {ahv.x, ahv.y, ahv.z, ahv.w};                     \
            uint32_t al[4] = {alv.x, alv.y, alv.z, alv.w};                     \
            _Pragma("unroll")                                                  \
            for (int nfl = 0; nfl < 4; ++nfl) {                                \
                mma16816(acc[mfl][nfl], ah, bh[nfl]);                          \
                mma16816(acc[mfl][nfl], ah, bl[nfl]);                          \
                mma16816(acc[mfl][nfl], al, bh[nfl]);                          \
            }                                                                  \
        }                                                                      \
    }

// ---------------- GEMM A: conv1 / shortcut (parity-decomposed 5x5) ----------
__global__ __launch_bounds__(256, 2)
void convA_mma(const float* __restrict__ g1, const float* __restrict__ b1,
               const float* __restrict__ m1, const float* __restrict__ v1,
               const float* __restrict__ gs, const float* __restrict__ bs,
               const float* __restrict__ ms, const float* __restrict__ vs)
{
    __shared__ __align__(16) uint8_t sm[SM_BYTES];
    uint8_t* AH = sm;
    uint8_t* AL = sm + 8192;
    uint8_t* BH = sm + 16384;
    uint8_t* BL = sm + 24576;
    float*   stage = (float*)sm;

    const int tid = threadIdx.x, lane = tid & 31, wid = tid >> 5;
    const int wm = wid >> 2, wn = wid & 3;
    const int m0 = blockIdx.x * 128, n0 = blockIdx.y * 128;
    const int par = blockIdx.z;
    const int ph = par >> 1, pw = par & 1;
    const int nTa = ph ? 2 : 3, nTb = pw ? 2 : 3;
    const int mloc = lane & 7, k2loc = lane >> 3;

    float acc[4][4][4];
#pragma unroll
    for (int a = 0; a < 4; ++a)
#pragma unroll
        for (int b = 0; b < 4; ++b)
#pragma unroll
            for (int e = 0; e < 4; ++e) acc[a][b][e] = 0.f;

    for (int ta = 0; ta < nTa; ++ta)
    for (int tb = 0; tb < nTb; ++tb) {
        const int da = ph ? ta : ta - 1;
        const int db = pw ? tb : tb - 1;
        const int tap = (ph ? 2 * ta + 1 : 2 * ta) * 5 + (pw ? 2 * tb + 1 : 2 * tb);
        for (int kc = 0; kc < 16; ++kc) {
            __syncthreads();
            // ---- build A tiles (im2col gather, fragment order) ----
#pragma unroll
            for (int it = 0; it < 8; ++it) {
                int u = it * 8 + wid;
                int octet = u & 15, grp = u >> 4;
                int m = m0 + octet * 8 + mloc;
                int batch = m / 784, sp = m - batch * 784;
                int i = sp / 28, j = sp - i * 28;
                int y = i + da, xx = j + db;
                int ch = kc * 32 + (grp * 4 + k2loc) * 2;
                uint32_t w0 = 0, w1v = 0;
                if ((unsigned)y < 28u && (unsigned)xx < 28u) {
                    const uint32_t* p = g_x2 + ((batch * CIn + ch) * 28 + y) * 28 + xx;
                    w0 = p[0]; w1v = p[784];
                }
                int addr = (grp >> 1) * 4096 + (octet >> 1) * 512
                         + (mloc * 4 + k2loc) * 16 + ((octet & 1) + 2 * (grp & 1)) * 4;
                *(uint32_t*)(AH + addr) = __byte_perm(w0, w1v, 0x5410);
                *(uint32_t*)(AL + addr) = __byte_perm(w0, w1v, 0x7632);
            }
            // ---- copy B tiles (pre-built frag-order images) ----
#pragma unroll
            for (int s = 0; s < 2; ++s) {
                int base = ((tap * 32 + kc * 2 + s) * 4 + blockIdx.y) * 2048;
                ((float4*)(BH + s * 4096))[tid] = ((const float4*)(g_wAh + base))[tid];
                ((float4*)(BL + s * 4096))[tid] = ((const float4*)(g_wAl + base))[tid];
            }
            __syncthreads();
            MMA_CHUNK(AH, AL, BH, BL)
        }
    }

    // ---- epilogue: smem transpose, BN, scatter to 56x56 ----
    const bool isT1 = (n0 < COc);
    for (int p = 0; p < 2; ++p) {
        __syncthreads();
        if ((wn >> 1) == p) {
#pragma unroll
            for (int mfl = 0; mfl < 4; ++mfl)
#pragma unroll
                for (int nfl = 0; nfl < 4; ++nfl)
#pragma unroll
                    for (int e = 0; e < 4; ++e) {
                        int nlrel = (wn & 1) * 32 + nfl * 8 + 2 * (lane & 3) + (e & 1);
                        int ml    = wm * 64 + mfl * 16 + (lane >> 2) + 8 * (e >> 1);
                        stage[nlrel * 132 + ml] = acc[mfl][nfl][e];
                    }
        }
        __syncthreads();
#pragma unroll
        for (int rr = 0; rr < 8; ++rr) {
            int row = wid * 8 + rr;
            int nl  = p * 64 + row;
            int ocg = n0 + nl;
            int c   = isT1 ? ocg : ocg - COc;
            float sg = isT1 ? g1[c] : gs[c];
            float sb = isT1 ? b1[c] : bs[c];
            float smn = isT1 ? m1[c] : ms[c];
            float sv = isT1 ? v1[c] : vs[c];
            float es = sg * rsqrtf(sv + 1e-5f);
            float eb = sb - smn * es;
            float4 f = *(const float4*)(stage + row * 132 + lane * 4);
            float fv[4] = {f.x, f.y, f.z, f.w};
#pragma unroll
            for (int q = 0; q < 4; ++q) {
                int m = m0 + lane * 4 + q;
                int batch = m / 784, sp = m - batch * 784;
                int i = sp / 28, j = sp - i * 28;
                int oh = 2 * i + ph, ow = 2 * j + pw;
                int idx = ((batch * COc + c) * 56 + oh) * 56 + ow;
                float v = fv[q] * es + eb;
                if (isT1) g_t1x2[idx] = pack_split(fmaxf(v, 0.f));
                else      g_scf[idx]  = v;
            }
        }
    }
}

// ---------------- GEMM B: conv2 + BN2 + shortcut + ReLU ---------------------
__global__ __launch_bounds__(256, 2)
void convB_mma(const float* __restrict__ g2, const float* __restrict__ b2,
               const float* __restrict__ m2, const float* __restrict__ v2,
               float* __restrict__ out)
{
    __shared__ __align__(16) uint8_t sm[SM_BYTES];
    uint8_t* AH = sm;
    uint8_t* AL = sm + 8192;
    uint8_t* BH = sm + 16384;
    uint8_t* BL = sm + 24576;
    float*   stage = (float*)sm;

    const int tid = threadIdx.x, lane = tid & 31, wid = tid >> 5;
    const int wm = wid >> 2, wn = wid & 3;
    const int m0 = blockIdx.x * 128, n0 = blockIdx.y * 128;
    const int mloc = lane & 7, k2loc = lane >> 3;

    float acc[4][4][4];
#pragma unroll
    for (int a = 0; a < 4; ++a)
#pragma unroll
        for (int b = 0; b < 4; ++b)
#pragma unroll
            for (int e = 0; e < 4; ++e) acc[a][b][e] = 0.f;

    for (int tap = 0; tap < 9; ++tap) {
        const int da = tap / 3 - 1, db = tap % 3 - 1;
        for (int kc = 0; kc < 8; ++kc) {
            __syncthreads();
#pragma unroll
            for (int it = 0; it < 8; ++it) {
                int u = it * 8 + wid;
                int octet = u & 15, grp = u >> 4;
                int m = m0 + octet * 8 + mloc;
                int batch = m / 3136, sp = m - batch * 3136;
                int i = sp / 56, j = sp - i * 56;
                int y = i + da, xx = j + db;
                int ch = kc * 32 + (grp * 4 + k2loc) * 2;
                uint32_t w0 = 0, w1v = 0;
                if ((unsigned)y < 56u && (unsigned)xx < 56u) {
                    const uint32_t* p = g_t1x2 + ((batch * COc + ch) * 56 + y) * 56 + xx;
                    w0 = p[0]; w1v = p[3136];
                }
                int addr = (grp >> 1) * 4096 + (octet >> 1) * 512
                         + (mloc * 4 + k2loc) * 16 + ((octet & 1) + 2 * (grp & 1)) * 4;
                *(uint32_t*)(AH + addr) = __byte_perm(w0, w1v, 0x5410);
                *(uint32_t*)(AL + addr) = __byte_perm(w0, w1v, 0x7632);
            }
#pragma unroll
            for (int s = 0; s < 2; ++s) {
                int base = ((tap * 16 + kc * 2 + s) * 2 + blockIdx.y) * 2048;
                ((float4*)(BH + s * 4096))[tid] = ((const float4*)(g_wBh + base))[tid];
                ((float4*)(BL + s * 4096))[tid] = ((const float4*)(g_wBl + base))[tid];
            }
            __syncthreads();
            MMA_CHUNK(AH, AL, BH, BL)
        }
    }

    // ---- epilogue: transpose, BN2 + shortcut + ReLU, coalesced stores ----
    for (int p = 0; p < 2; ++p) {
        __syncthreads();
        if ((wn >> 1) == p) {
#pragma unroll
            for (int mfl = 0; mfl < 4; ++mfl)
#pragma unroll
                for (int nfl = 0; nfl < 4; ++nfl)
#pragma unroll
                    for (int e = 0; e < 4; ++e) {
                        int nlrel = (wn & 1) * 32 + nfl * 8 + 2 * (lane & 3) + (e & 1);
                        int ml    = wm * 64 + mfl * 16 + (lane >> 2) + 8 * (e >> 1);
                        stage[nlrel * 132 + ml] = acc[mfl][nfl][e];
                    }
        }
        __syncthreads();
#pragma unroll
        for (int rr = 0; rr < 8; ++rr) {
            int row = wid * 8 + rr;
            int oc  = n0 + p * 64 + row;
            float es = g2[oc] * rsqrtf(v2[oc] + 1e-5f);
            float eb = b2[oc] - m2[oc] * es;
            int m = m0 + lane * 4;
            int batch = m / 3136, sp = m - batch * 3136;
            int idx = (batch * COc + oc) * 3136 + sp;
            float4 f  = *(const float4*)(stage + row * 132 + lane * 4);
            float4 sc = *(const float4*)(g_scf + idx);
            float4 o;
            o.x = fmaxf(f.x * es + eb + sc.x, 0.f);
            o.y = fmaxf(f.y * es + eb + sc.y, 0.f);
            o.z = fmaxf(f.z * es + eb + sc.z, 0.f);
            o.w = fmaxf(f.w * es + eb + sc.w, 0.f);
            *(float4*)(out + idx) = o;
        }
    }
}

// ---------------------------------------------------------------------------
extern "C" void kernel_launch(void* const* d_in, const int* in_sizes, int n_in,
                              void* d_out, int out_size)
{
    const float* x   = (const float*)d_in[0];
    const float* w1  = (const float*)d_in[1];
    const float* g1  = (const float*)d_in[2];
    const float* b1  = (const float*)d_in[3];
    const float* m1  = (const float*)d_in[4];
    const float* v1  = (const float*)d_in[5];
    const float* w2  = (const float*)d_in[6];
    const float* g2  = (const float*)d_in[7];
    const float* b2  = (const float*)d_in[8];
    const float* m2  = (const float*)d_in[9];
    const float* v2  = (const float*)d_in[10];
    const float* wsc = (const float*)d_in[11];
    const float* gs  = (const float*)d_in[12];
    const float* bs  = (const float*)d_in[13];
    const float* ms  = (const float*)d_in[14];
    const float* vs  = (const float*)d_in[15];
    float* out = (float*)d_out;

    prep<<<25600, 256>>>(x, w1, wsc, w2);

    dim3 gA(98, 4, 4);     // 12544/128 m-tiles, 512/128 n-tiles, 4 parities
    convA_mma<<<gA, 256>>>(g1, b1, m1, v1, gs, bs, ms, vs);

    dim3 gB(392, 2);       // 50176/128 m-tiles, 256/128 n-tiles
    convB_mma<<<gB, 256>>>(g2, b2, m2, v2, out);
}